// round 10
// baseline (speedup 1.0000x reference)
#include <cuda_runtime.h>
#include <math.h>

#define B_    8
#define L_    160000
#define C_    4
#define NFFT_ 320
#define HOP_  160
#define T_    1001
#define F_    161
#define KTAP  6
#define NQ    7          // fused: output q-segments per block
#define TF    8          // fused: frames per block
#define TS4   4          // stft: frames per block
#define SVLEN (160*TS4 + 160)   // 800
#define NCH   125        // stats chunks per batch
#define CHL   1280       // samples per chunk (5 x 256)

// ---------------- scratch ----------------
__device__ float2 g_X [(size_t)B_*T_*F_*C_];    // STFT  [b][t][k][c]
__device__ float4 g_ssum[B_*NCH];
__device__ float4 g_smax[B_*NCH];
__device__ float4 g_smin[B_*NCH];

__constant__ float c_c95[10] = {0.95f, 0.0475f, 2.375e-3f, 1.1875e-4f, 5.9375e-6f,
                                2.96875e-7f, 1.484375e-8f, 7.421875e-10f,
                                3.7109375e-11f, 1.85546875e-12f};
__constant__ float c_p05[10] = {1.0f, 0.05f, 2.5e-3f, 1.25e-4f, 6.25e-6f,
                                3.125e-7f, 1.5625e-8f, 7.8125e-10f,
                                3.90625e-11f, 1.953125e-12f};

// ---------------- complex helpers ----------------
__device__ __forceinline__ float2 cadd(float2 a, float2 b){ return make_float2(a.x+b.x, a.y+b.y); }
__device__ __forceinline__ float2 csub(float2 a, float2 b){ return make_float2(a.x-b.x, a.y-b.y); }
__device__ __forceinline__ float2 cmul(float2 a, float2 b){ return make_float2(a.x*b.x-a.y*b.y, a.x*b.y+a.y*b.x); }
__device__ __forceinline__ float2 ccmul(float2 a, float2 b){ return make_float2(a.x*b.x+a.y*b.y, a.x*b.y-a.y*b.x); } // conj(a)*b
__device__ __forceinline__ float2 cmulc(float2 a, float2 b){ return make_float2(a.x*b.x+a.y*b.y, a.y*b.x-a.x*b.y); } // a*conj(b)
__device__ __forceinline__ float2 cscale(float s, float2 a){ return make_float2(s*a.x, s*a.y); }

// ---------------- stats ----------------
__global__ void k_stats(const float* __restrict__ x){
    int b = blockIdx.y, ch = blockIdx.x;
    int tid = threadIdx.x;
    const float4* px = (const float4*)(x + (size_t)b*L_*C_) + ch*CHL + tid;

    float4 v0 = px[0], v1 = px[256], v2 = px[512], v3 = px[768], v4 = px[1024];

    float4 s, mx, mn;
    s.x = v0.x+v1.x+v2.x+v3.x+v4.x; s.y = v0.y+v1.y+v2.y+v3.y+v4.y;
    s.z = v0.z+v1.z+v2.z+v3.z+v4.z; s.w = v0.w+v1.w+v2.w+v3.w+v4.w;
    mx.x = fmaxf(fmaxf(fmaxf(v0.x,v1.x),fmaxf(v2.x,v3.x)),v4.x);
    mx.y = fmaxf(fmaxf(fmaxf(v0.y,v1.y),fmaxf(v2.y,v3.y)),v4.y);
    mx.z = fmaxf(fmaxf(fmaxf(v0.z,v1.z),fmaxf(v2.z,v3.z)),v4.z);
    mx.w = fmaxf(fmaxf(fmaxf(v0.w,v1.w),fmaxf(v2.w,v3.w)),v4.w);
    mn.x = fminf(fminf(fminf(v0.x,v1.x),fminf(v2.x,v3.x)),v4.x);
    mn.y = fminf(fminf(fminf(v0.y,v1.y),fminf(v2.y,v3.y)),v4.y);
    mn.z = fminf(fminf(fminf(v0.z,v1.z),fminf(v2.z,v3.z)),v4.z);
    mn.w = fminf(fminf(fminf(v0.w,v1.w),fminf(v2.w,v3.w)),v4.w);

    #pragma unroll
    for(int o = 16; o; o >>= 1){
        s.x += __shfl_xor_sync(~0u, s.x, o); s.y += __shfl_xor_sync(~0u, s.y, o);
        s.z += __shfl_xor_sync(~0u, s.z, o); s.w += __shfl_xor_sync(~0u, s.w, o);
        mx.x = fmaxf(mx.x, __shfl_xor_sync(~0u, mx.x, o)); mx.y = fmaxf(mx.y, __shfl_xor_sync(~0u, mx.y, o));
        mx.z = fmaxf(mx.z, __shfl_xor_sync(~0u, mx.z, o)); mx.w = fmaxf(mx.w, __shfl_xor_sync(~0u, mx.w, o));
        mn.x = fminf(mn.x, __shfl_xor_sync(~0u, mn.x, o)); mn.y = fminf(mn.y, __shfl_xor_sync(~0u, mn.y, o));
        mn.z = fminf(mn.z, __shfl_xor_sync(~0u, mn.z, o)); mn.w = fminf(mn.w, __shfl_xor_sync(~0u, mn.w, o));
    }

    __shared__ float4 ps[8], pxm[8], pnm[8];
    int w = tid >> 5, lane = tid & 31;
    if(lane == 0){ ps[w] = s; pxm[w] = mx; pnm[w] = mn; }
    __syncthreads();
    if(tid < 8){
        s = ps[tid]; mx = pxm[tid]; mn = pnm[tid];
        #pragma unroll
        for(int o = 4; o; o >>= 1){
            s.x += __shfl_xor_sync(0xff, s.x, o); s.y += __shfl_xor_sync(0xff, s.y, o);
            s.z += __shfl_xor_sync(0xff, s.z, o); s.w += __shfl_xor_sync(0xff, s.w, o);
            mx.x = fmaxf(mx.x, __shfl_xor_sync(0xff, mx.x, o)); mx.y = fmaxf(mx.y, __shfl_xor_sync(0xff, mx.y, o));
            mx.z = fmaxf(mx.z, __shfl_xor_sync(0xff, mx.z, o)); mx.w = fmaxf(mx.w, __shfl_xor_sync(0xff, mx.w, o));
            mn.x = fminf(mn.x, __shfl_xor_sync(0xff, mn.x, o)); mn.y = fminf(mn.y, __shfl_xor_sync(0xff, mn.y, o));
            mn.z = fminf(mn.z, __shfl_xor_sync(0xff, mn.z, o)); mn.w = fminf(mn.w, __shfl_xor_sync(0xff, mn.w, o));
        }
        if(tid == 0){
            g_ssum[b*NCH+ch] = s; g_smax[b*NCH+ch] = mx; g_smin[b*NCH+ch] = mn;
        }
    }
}

// ---------------- STFT: 4 frames/block, register radix DFT-16 + constant DFT-20 ----------------
__global__ void k_stft(const float* __restrict__ x, const float* __restrict__ win){
    const float C16[16] = { 1.f, 0.9238795325f, 0.7071067812f, 0.3826834324f, 0.f,
                           -0.3826834324f,-0.7071067812f,-0.9238795325f,-1.f,-0.9238795325f,
                           -0.7071067812f,-0.3826834324f, 0.f, 0.3826834324f, 0.7071067812f, 0.9238795325f };
    const float S16[16] = { 0.f, 0.3826834324f, 0.7071067812f, 0.9238795325f, 1.f,
                            0.9238795325f, 0.7071067812f, 0.3826834324f, 0.f,-0.3826834324f,
                           -0.7071067812f,-0.9238795325f,-1.f,-0.9238795325f,-0.7071067812f,-0.3826834324f };
    const float C20[20] = { 1.f, 0.9510565163f, 0.8090169944f, 0.5877852523f, 0.3090169944f,
                            0.f,-0.3090169944f,-0.5877852523f,-0.8090169944f,-0.9510565163f,
                           -1.f,-0.9510565163f,-0.8090169944f,-0.5877852523f,-0.3090169944f,
                            0.f, 0.3090169944f, 0.5877852523f, 0.8090169944f, 0.9510565163f };
    const float S20[20] = { 0.f, 0.3090169944f, 0.5877852523f, 0.8090169944f, 0.9510565163f,
                            1.f, 0.9510565163f, 0.8090169944f, 0.5877852523f, 0.3090169944f,
                            0.f,-0.3090169944f,-0.5877852523f,-0.8090169944f,-0.9510565163f,
                           -1.f,-0.9510565163f,-0.8090169944f,-0.5877852523f,-0.3090169944f };

    int blk = blockIdx.x, b = blockIdx.y;
    int tid = threadIdx.x;
    int t0 = blk*TS4;
    __shared__ float  sv[C_][SVLEN];
    __shared__ float  swin[NFFT_];
    __shared__ float2 sG[TS4][C_][9][20];
    __shared__ float  sMean[4];
    __shared__ float  sInv;

    if(tid < 32){
        float4 s  = make_float4(0.f,0.f,0.f,0.f);
        float4 mx = make_float4(-1e30f,-1e30f,-1e30f,-1e30f);
        float4 mn = make_float4( 1e30f, 1e30f, 1e30f, 1e30f);
        for(int i = tid; i < NCH; i += 32){
            float4 a = g_ssum[b*NCH+i];
            s.x += a.x; s.y += a.y; s.z += a.z; s.w += a.w;
            float4 c = g_smax[b*NCH+i];
            mx.x = fmaxf(mx.x,c.x); mx.y = fmaxf(mx.y,c.y); mx.z = fmaxf(mx.z,c.z); mx.w = fmaxf(mx.w,c.w);
            float4 d = g_smin[b*NCH+i];
            mn.x = fminf(mn.x,d.x); mn.y = fminf(mn.y,d.y); mn.z = fminf(mn.z,d.z); mn.w = fminf(mn.w,d.w);
        }
        for(int o = 16; o; o >>= 1){
            s.x += __shfl_xor_sync(~0u, s.x, o); s.y += __shfl_xor_sync(~0u, s.y, o);
            s.z += __shfl_xor_sync(~0u, s.z, o); s.w += __shfl_xor_sync(~0u, s.w, o);
            mx.x = fmaxf(mx.x, __shfl_xor_sync(~0u, mx.x, o)); mx.y = fmaxf(mx.y, __shfl_xor_sync(~0u, mx.y, o));
            mx.z = fmaxf(mx.z, __shfl_xor_sync(~0u, mx.z, o)); mx.w = fmaxf(mx.w, __shfl_xor_sync(~0u, mx.w, o));
            mn.x = fminf(mn.x, __shfl_xor_sync(~0u, mn.x, o)); mn.y = fminf(mn.y, __shfl_xor_sync(~0u, mn.y, o));
            mn.z = fminf(mn.z, __shfl_xor_sync(~0u, mn.z, o)); mn.w = fminf(mn.w, __shfl_xor_sync(~0u, mn.w, o));
        }
        if(tid == 0){
            float m0 = s.x/(float)L_, m1 = s.y/(float)L_, m2 = s.z/(float)L_, m3 = s.w/(float)L_;
            float a = fmaxf(fmaxf(mx.x-m0, m0-mn.x), fmaxf(mx.y-m1, m1-mn.y));
            a = fmaxf(a, fmaxf(fmaxf(mx.z-m2, m2-mn.z), fmaxf(mx.w-m3, m3-mn.w)));
            sMean[0]=m0; sMean[1]=m1; sMean[2]=m2; sMean[3]=m3; sInv = 1.0f/a;
        }
    }
    for(int i = tid; i < NFFT_; i += 256) swin[i] = win[i];
    __syncthreads();

    {
        float m0 = sMean[0], m1 = sMean[1], m2 = sMean[2], m3 = sMean[3], inv = sInv;
        for(int i = tid; i < SVLEN; i += 256){
            int l = t0*HOP_ + i - (NFFT_/2);
            if(l < 0) l = -l;
            else if(l >= L_) l = 2*L_ - 2 - l;
            float4 v = *(const float4*)(x + ((size_t)b*L_ + l)*C_);
            sv[0][i] = (v.x-m0)*inv; sv[1][i] = (v.y-m1)*inv;
            sv[2][i] = (v.z-m2)*inv; sv[3][i] = (v.w-m3)*inv;
        }
    }
    __syncthreads();

    for(int task = tid; task < TS4*C_*20; task += 256){
        int r = task % 20;
        int c = (task/20) & 3;
        int f = task/80;
        int base = f*HOP_ + r;
        float v[16];
        #pragma unroll
        for(int q = 0; q < 16; q++) v[q] = sv[c][base + 20*q] * swin[20*q + r];
        float2 Bq[4][4];
        #pragma unroll
        for(int qb = 0; qb < 4; qb++){
            float v0=v[qb], v1=v[4+qb], v2=v[8+qb], v3=v[12+qb];
            float s0=v0+v2, d0=v0-v2, s1=v1+v3, d1=v1-v3;
            Bq[qb][0] = make_float2(s0+s1, 0.f);
            Bq[qb][2] = make_float2(s0-s1, 0.f);
            Bq[qb][1] = make_float2(d0, -d1);
            Bq[qb][3] = make_float2(d0,  d1);
        }
        float sn, cs; sincospif(-(float)r/160.0f, &sn, &cs);
        float2 step = make_float2(cs, sn), w = make_float2(1.f, 0.f);
        #pragma unroll
        for(int m = 0; m < 9; m++){
            float2 acc = Bq[0][m&3];
            #pragma unroll
            for(int qb = 1; qb < 4; qb++){
                int j = (qb*m) & 15;
                float2 y = Bq[qb][m&3];
                acc.x += y.x*C16[j] + y.y*S16[j];
                acc.y += y.y*C16[j] - y.x*S16[j];
            }
            sG[f][c][m][r] = cmul(acc, w);
            w = cmul(w, step);
        }
    }
    __syncthreads();

    for(int task = tid; task < TS4*C_*16; task += 256){
        int m = task & 15;
        int c = (task >> 4) & 3;
        int f = task >> 6;
        int t = t0 + f;
        if(t >= T_) continue;
        float2 y[20];
        if(m <= 8){
            #pragma unroll
            for(int r = 0; r < 20; r++) y[r] = sG[f][c][m][r];
        } else {
            int mm = 16 - m;
            #pragma unroll
            for(int r = 0; r < 20; r++){
                float2 g = sG[f][c][mm][r];
                float gr = g.x, gi = -g.y;
                y[r].x = gr*C20[r] + gi*S20[r];
                y[r].y = gi*C20[r] - gr*S20[r];
            }
        }
        float2 D[5][4];
        #pragma unroll
        for(int r2 = 0; r2 < 5; r2++){
            float2 y0=y[r2], y1=y[5+r2], y2=y[10+r2], y3=y[15+r2];
            float2 s0=cadd(y0,y2), d0=csub(y0,y2), s1=cadd(y1,y3), d1=csub(y1,y3);
            D[r2][0] = cadd(s0,s1);
            D[r2][2] = csub(s0,s1);
            D[r2][1] = make_float2(d0.x + d1.y, d0.y - d1.x);
            D[r2][3] = make_float2(d0.x - d1.y, d0.y + d1.x);
        }
        int amax = (m == 0) ? 10 : 9;
        #pragma unroll
        for(int a = 0; a <= 10; a++){
            if(a > amax) break;
            float2 acc = D[0][a&3];
            #pragma unroll
            for(int r2 = 1; r2 < 5; r2++){
                int j = (a*r2) % 20;
                float2 dd = D[r2][a&3];
                acc.x += dd.x*C20[j] + dd.y*S20[j];
                acc.y += dd.y*C20[j] - dd.x*S20[j];
            }
            int k = 16*a + m;
            g_X[(((size_t)b*T_ + t)*F_ + k)*C_ + c] = acc;   // [b][t][k][c]
        }
    }
}

// ---------------- fused MVDR beam + ISTFT + OLA ----------------
struct LDLf { float iD0,iD1,iD2,iD3; float2 L10,L20,L30,L21,L31,L32; };

__device__ __forceinline__ float2 mvdr_beam2(const LDLf& f,
    float2 h1, float2 h2, float2 h3,          // h0 = 1
    float2 X0, float2 X1, float2 X2, float2 X3)
{
    float2 z1 = csub(h1, f.L10);
    float2 z2 = csub(csub(h2, f.L20), cmul(f.L21, z1));
    float2 z3 = csub(csub(csub(h3, f.L30), cmul(f.L31, z1)), cmul(f.L32, z2));
    float2 y3 = cscale(f.iD3, z3);
    float2 y2 = csub(cscale(f.iD2, z2), ccmul(f.L32, y3));
    float2 y1 = csub(csub(cscale(f.iD1, z1), ccmul(f.L21, y2)), ccmul(f.L31, y3));
    float2 y0 = csub(csub(csub(make_float2(f.iD0, 0.f), ccmul(f.L10, y1)), ccmul(f.L20, y2)), ccmul(f.L30, y3));
    float den = y0.x + (h1.x*y1.x + h1.y*y1.y) + (h2.x*y2.x + h2.y*y2.y) + (h3.x*y3.x + h3.y*y3.y);
    float2 s  = cadd(cadd(ccmul(y0,X0), ccmul(y1,X1)), cadd(ccmul(y2,X2), ccmul(y3,X3)));
    float inv = 1.0f/den;
    return make_float2(s.x*inv, s.y*inv);
}

#define SY_BYTES (2*TF*162*8)     // 20736
#define SFR_BYTES (2*TF*322*4)    // 20608
#define NTB 352                   // bistft threads

__global__ void __launch_bounds__(NTB) k_bistft(float* __restrict__ out){
    const float C20[20] = { 1.f, 0.9510565163f, 0.8090169944f, 0.5877852523f, 0.3090169944f,
                            0.f,-0.3090169944f,-0.5877852523f,-0.8090169944f,-0.9510565163f,
                           -1.f,-0.9510565163f,-0.8090169944f,-0.5877852523f,-0.3090169944f,
                            0.f, 0.3090169944f, 0.5877852523f, 0.8090169944f, 0.9510565163f };
    const float S20[20] = { 0.f, 0.3090169944f, 0.5877852523f, 0.8090169944f, 0.9510565163f,
                            1.f, 0.9510565163f, 0.8090169944f, 0.5877852523f, 0.3090169944f,
                            0.f,-0.3090169944f,-0.5877852523f,-0.8090169944f,-0.9510565163f,
                           -1.f,-0.9510565163f,-0.8090169944f,-0.5877852523f,-0.3090169944f };
    const float C16[16] = { 1.f, 0.9238795325f, 0.7071067812f, 0.3826834324f, 0.f,
                           -0.3826834324f,-0.7071067812f,-0.9238795325f,-1.f,-0.9238795325f,
                           -0.7071067812f,-0.3826834324f, 0.f, 0.3826834324f, 0.7071067812f, 0.9238795325f };
    const float S16[16] = { 0.f, 0.3826834324f, 0.7071067812f, 0.9238795325f, 1.f,
                            0.9238795325f, 0.7071067812f, 0.3826834324f, 0.f,-0.3826834324f,
                           -0.7071067812f,-0.9238795325f,-1.f,-0.9238795325f,-0.7071067812f,-0.3826834324f };

    int blk = blockIdx.x, b = blockIdx.y;
    int tid = threadIdx.x;
    int t0  = blk*NQ;

    __shared__ float2 sH[2][9][20][TF+1];
    __shared__ __align__(16) char pool[SY_BYTES > SFR_BYTES ? SY_BYTES : SFR_BYTES];
    float2* sY  = (float2*)pool;   // [ (beam*TF+f)*162 + k ]
    float*  sFr = (float*)pool;    // [ (beam*TF+f)*322 + n ]  (aliases sY, used after)

    // ======== phase 1: beam — thread = (beam, k); identical instruction stream both halves ========
    {
        int beam = tid / 176;       // 0 or 1
        int k    = tid % 176;
        if(k < F_ && beam < 2){
            const float4* gx = (const float4*)g_X + (size_t)b*T_*F_*2;

            const float phi = (float)(6.283185307179586 * 50.0 * 0.027 * 0.6427876096865393 / 340.0);
            float bsign = (beam == 0) ? -1.f : 1.f;
            float ang = phi * (float)k;
            float s1, c1; sincosf(ang, &s1, &c1);
            float c2 = c1*c1 - s1*s1, s2 = 2.f*c1*s1;
            float c3 = c2*c1 - s2*s1, s3 = s2*c1 + c2*s1;
            float2 h1 = make_float2(c1, bsign*s1);
            float2 h2 = make_float2(c2, bsign*s2);
            float2 h3 = make_float2(c3, bsign*s3);

            float d0=0,d1=0,d2=0,d3=0;
            float2 m10={0,0}, m20={0,0}, m21={0,0}, m30={0,0}, m31={0,0}, m32={0,0};

            int tw = t0 - 1;
            if(tw >= 0){
                #pragma unroll
                for(int j = 0; j < KTAP; j++){
                    int s = tw - j;
                    if(s < 0) break;
                    float cf = (s == 0) ? c_p05[tw] : c_c95[j];
                    size_t off = ((size_t)s*F_ + k)*2;
                    float4 a = gx[off], bb = gx[off+1];
                    float2 y0 = make_float2(a.x,a.y), y1 = make_float2(a.z,a.w);
                    float2 y2 = make_float2(bb.x,bb.y), y3 = make_float2(bb.z,bb.w);
                    d0 += cf*(y0.x*y0.x + y0.y*y0.y);
                    d1 += cf*(y1.x*y1.x + y1.y*y1.y);
                    d2 += cf*(y2.x*y2.x + y2.y*y2.y);
                    d3 += cf*(y3.x*y3.x + y3.y*y3.y);
                    m10 = cadd(m10, cscale(cf, cmulc(y1,y0)));
                    m20 = cadd(m20, cscale(cf, cmulc(y2,y0)));
                    m21 = cadd(m21, cscale(cf, cmulc(y2,y1)));
                    m30 = cadd(m30, cscale(cf, cmulc(y3,y0)));
                    m31 = cadd(m31, cscale(cf, cmulc(y3,y1)));
                    m32 = cadd(m32, cscale(cf, cmulc(y3,y2)));
                }
            }

            #pragma unroll
            for(int i = 0; i < TF; i++){
                int t = t0 + i;
                if(t < T_){
                    size_t off = ((size_t)t*F_ + k)*2;
                    float4 xa = gx[off], xb = gx[off+1];
                    float2 X0 = make_float2(xa.x,xa.y), X1 = make_float2(xa.z,xa.w);
                    float2 X2 = make_float2(xb.x,xb.y), X3 = make_float2(xb.z,xb.w);

                    if(t == 0){
                        d0 = X0.x*X0.x + X0.y*X0.y;
                        d1 = X1.x*X1.x + X1.y*X1.y;
                        d2 = X2.x*X2.x + X2.y*X2.y;
                        d3 = X3.x*X3.x + X3.y*X3.y;
                        m10 = cmulc(X1,X0); m20 = cmulc(X2,X0); m21 = cmulc(X2,X1);
                        m30 = cmulc(X3,X0); m31 = cmulc(X3,X1); m32 = cmulc(X3,X2);
                    } else {
                        d0 = 0.05f*d0 + 0.95f*(X0.x*X0.x + X0.y*X0.y);
                        d1 = 0.05f*d1 + 0.95f*(X1.x*X1.x + X1.y*X1.y);
                        d2 = 0.05f*d2 + 0.95f*(X2.x*X2.x + X2.y*X2.y);
                        d3 = 0.05f*d3 + 0.95f*(X3.x*X3.x + X3.y*X3.y);
                        m10 = cadd(cscale(0.05f,m10), cscale(0.95f, cmulc(X1,X0)));
                        m20 = cadd(cscale(0.05f,m20), cscale(0.95f, cmulc(X2,X0)));
                        m21 = cadd(cscale(0.05f,m21), cscale(0.95f, cmulc(X2,X1)));
                        m30 = cadd(cscale(0.05f,m30), cscale(0.95f, cmulc(X3,X0)));
                        m31 = cadd(cscale(0.05f,m31), cscale(0.95f, cmulc(X3,X1)));
                        m32 = cadd(cscale(0.05f,m32), cscale(0.95f, cmulc(X3,X2)));
                    }

                    float tr4 = 0.25f*(d0+d1+d2+d3);
                    float a0 = d0+tr4, a1 = d1+tr4, a2 = d2+tr4, a3 = d3+tr4;

                    LDLf f;
                    f.iD0 = 1.0f/a0;
                    f.L10 = cscale(f.iD0, m10); f.L20 = cscale(f.iD0, m20); f.L30 = cscale(f.iD0, m30);
                    float D1 = a1 - (m10.x*f.L10.x + m10.y*f.L10.y);
                    f.iD1 = 1.0f/D1;
                    float2 t21 = csub(m21, cmulc(m20, f.L10));
                    f.L21 = cscale(f.iD1, t21);
                    float2 t31 = csub(m31, cmulc(m30, f.L10));
                    f.L31 = cscale(f.iD1, t31);
                    float D2 = a2 - (m20.x*f.L20.x + m20.y*f.L20.y) - (t21.x*f.L21.x + t21.y*f.L21.y);
                    f.iD2 = 1.0f/D2;
                    float2 t32 = csub(csub(m32, cmulc(m30, f.L20)), cmulc(t31, f.L21));
                    f.L32 = cscale(f.iD2, t32);
                    float D3 = a3 - (m30.x*f.L30.x + m30.y*f.L30.y)
                                  - (t31.x*f.L31.x + t31.y*f.L31.y)
                                  - (t32.x*f.L32.x + t32.y*f.L32.y);
                    f.iD3 = 1.0f/D3;

                    sY[(beam*TF+i)*162 + k] = mvdr_beam2(f, h1, h2, h3, X0, X1, X2, X3);
                } else {
                    sY[(beam*TF+i)*162 + k] = make_float2(0.f,0.f);
                }
            }
        }
    }
    __syncthreads();

    // ======== phase 2 (stage A): per (beam,k1,f) inverse DFT-20 -> sH ========
    if(tid < 2*9*TF){
        int beam = tid / (9*TF);
        int r    = tid % (9*TF);
        int k1 = r / TF, f = r % TF;
        const float2* yrow = sY + (beam*TF + f)*162;
        float2 z[20];
        #pragma unroll
        for(int k2 = 0; k2 < 20; k2++){
            int kk = 16*k2 + k1;
            float2 v;
            if(kk <= 160){
                v = yrow[kk];
                if(k1 == 0 && (k2 == 0 || k2 == 10)) v.y = 0.f;
            } else {
                v = yrow[320-kk];
                v.y = -v.y;
            }
            z[k2] = v;
        }
        float2 Y[5][4];
        #pragma unroll
        for(int bq = 0; bq < 5; bq++){
            float2 z0=z[bq], z1=z[bq+5], z2=z[bq+10], z3=z[bq+15];
            float2 s0=cadd(z0,z2), s1=csub(z0,z2), s2=cadd(z1,z3), s3=csub(z1,z3);
            Y[bq][0] = cadd(s0,s2);
            Y[bq][2] = csub(s0,s2);
            Y[bq][1] = make_float2(s1.x - s3.y, s1.y + s3.x);
            Y[bq][3] = make_float2(s1.x + s3.y, s1.y - s3.x);
        }
        float sc = (k1==0 || k1==8) ? 1.f : 2.f;
        #pragma unroll
        for(int p = 0; p < 20; p++){
            float2 acc = Y[0][p&3];
            #pragma unroll
            for(int bq = 1; bq < 5; bq++){
                float cw = C20[(bq*p)%20], sw = S20[(bq*p)%20];
                float2 y = Y[bq][p&3];
                acc.x += cw*y.x - sw*y.y;
                acc.y += cw*y.y + sw*y.x;
            }
            sH[beam][k1][p][f] = make_float2(sc*acc.x, sc*acc.y);
        }
    }
    __syncthreads();

    // ======== phase 3 (stage B): twiddle + 9-term DFT-16 -> sFr (aliases sY) ========
    for(int task = tid; task < 2*20*TF; task += NTB){
        int beam = task / (20*TF);
        int r    = task % (20*TF);
        int pm = r / TF, f = r % TF;
        float sn, cs; sincospif((float)pm/160.0f, &sn, &cs);
        float2 wst = make_float2(cs, sn), w = make_float2(1.f, 0.f);
        float2 a[9];
        a[0] = sH[beam][0][pm][f];
        #pragma unroll
        for(int k1 = 1; k1 < 9; k1++){
            w = cmul(w, wst);
            a[k1] = cmul(sH[beam][k1][pm][f], w);
        }
        float* frow = sFr + (beam*TF + f)*322;
        #pragma unroll
        for(int u = 0; u < 16; u++){
            float acc = a[0].x;
            #pragma unroll
            for(int k1 = 1; k1 < 9; k1++){
                int j = (k1*u) & 15;
                acc += a[k1].x*C16[j] - a[k1].y*S16[j];
            }
            frow[20*u + pm] = acc * (1.0f/640.0f);
        }
    }
    __syncthreads();

    // ======== phase 4: OLA output ========
    int qmax = min(t0 + NQ, T_ - 1);
    int nq = qmax - t0;
    for(int task = tid; task < 2*nq*80; task += NTB){
        int beam = task / (nq*80);
        int r2   = task % (nq*80);
        int qi = r2 / 80;
        int rr = (r2 % 80)*2;
        int q  = t0 + 1 + qi;
        int fq = qi + 1;
        const float* fa = sFr + (beam*TF + fq)*322;
        const float* fb = sFr + (beam*TF + fq - 1)*322;
        float v0 = fa[rr]   + fb[160+rr];
        float v1 = fa[rr+1] + fb[161+rr];
        *(float2*)(out + (size_t)(beam*B_+b)*L_ + (size_t)(q-1)*160 + rr) = make_float2(v0, v1);
    }
}

// ---------------- launch ----------------
extern "C" void kernel_launch(void* const* d_in, const int* in_sizes, int n_in,
                              void* d_out, int out_size){
    const float* x   = (const float*)d_in[0];
    const float* win = (const float*)d_in[1];
    float* out = (float*)d_out;

    k_stats <<<dim3(NCH, B_), 256>>>(x);
    k_stft  <<<dim3((T_+TS4-1)/TS4, B_), 256>>>(x, win);
    k_bistft<<<dim3((T_-1+NQ-1)/NQ, B_), NTB>>>(out);
}

// round 13
// speedup vs baseline: 1.1429x; 1.1429x over previous
#include <cuda_runtime.h>
#include <math.h>

#define B_    8
#define L_    160000
#define C_    4
#define NFFT_ 320
#define HOP_  160
#define T_    1001
#define F_    161
#define KTAP  6
#define NQ    7          // fused: output q-segments per block
#define TF    8          // fused: frames per block
#define TS4   4          // stft: frames per block
#define SVLEN (160*TS4 + 160)   // 800
#define NCH   125        // stats chunks per batch
#define CHL   1280       // samples per chunk (5 x 256)

// ---------------- scratch ----------------
__device__ float2 g_X [(size_t)B_*T_*F_*C_];    // STFT  [b][t][k][c]
__device__ float4 g_ssum[B_*NCH];
__device__ float4 g_smax[B_*NCH];
__device__ float4 g_smin[B_*NCH];

__constant__ float c_c95[10] = {0.95f, 0.0475f, 2.375e-3f, 1.1875e-4f, 5.9375e-6f,
                                2.96875e-7f, 1.484375e-8f, 7.421875e-10f,
                                3.7109375e-11f, 1.85546875e-12f};
__constant__ float c_p05[10] = {1.0f, 0.05f, 2.5e-3f, 1.25e-4f, 6.25e-6f,
                                3.125e-7f, 1.5625e-8f, 7.8125e-10f,
                                3.90625e-11f, 1.953125e-12f};

// ---------------- complex helpers ----------------
__device__ __forceinline__ float2 cadd(float2 a, float2 b){ return make_float2(a.x+b.x, a.y+b.y); }
__device__ __forceinline__ float2 csub(float2 a, float2 b){ return make_float2(a.x-b.x, a.y-b.y); }
__device__ __forceinline__ float2 cmul(float2 a, float2 b){ return make_float2(a.x*b.x-a.y*b.y, a.x*b.y+a.y*b.x); }
__device__ __forceinline__ float2 ccmul(float2 a, float2 b){ return make_float2(a.x*b.x+a.y*b.y, a.x*b.y-a.y*b.x); } // conj(a)*b
__device__ __forceinline__ float2 cmulc(float2 a, float2 b){ return make_float2(a.x*b.x+a.y*b.y, a.y*b.x-a.x*b.y); } // a*conj(b)
__device__ __forceinline__ float2 cscale(float s, float2 a){ return make_float2(s*a.x, s*a.y); }

// ---------------- stats ----------------
__global__ void k_stats(const float* __restrict__ x){
    int b = blockIdx.y, ch = blockIdx.x;
    int tid = threadIdx.x;
    const float4* px = (const float4*)(x + (size_t)b*L_*C_) + ch*CHL + tid;

    float4 v0 = px[0], v1 = px[256], v2 = px[512], v3 = px[768], v4 = px[1024];

    float4 s, mx, mn;
    s.x = v0.x+v1.x+v2.x+v3.x+v4.x; s.y = v0.y+v1.y+v2.y+v3.y+v4.y;
    s.z = v0.z+v1.z+v2.z+v3.z+v4.z; s.w = v0.w+v1.w+v2.w+v3.w+v4.w;
    mx.x = fmaxf(fmaxf(fmaxf(v0.x,v1.x),fmaxf(v2.x,v3.x)),v4.x);
    mx.y = fmaxf(fmaxf(fmaxf(v0.y,v1.y),fmaxf(v2.y,v3.y)),v4.y);
    mx.z = fmaxf(fmaxf(fmaxf(v0.z,v1.z),fmaxf(v2.z,v3.z)),v4.z);
    mx.w = fmaxf(fmaxf(fmaxf(v0.w,v1.w),fmaxf(v2.w,v3.w)),v4.w);
    mn.x = fminf(fminf(fminf(v0.x,v1.x),fminf(v2.x,v3.x)),v4.x);
    mn.y = fminf(fminf(fminf(v0.y,v1.y),fminf(v2.y,v3.y)),v4.y);
    mn.z = fminf(fminf(fminf(v0.z,v1.z),fminf(v2.z,v3.z)),v4.z);
    mn.w = fminf(fminf(fminf(v0.w,v1.w),fminf(v2.w,v3.w)),v4.w);

    #pragma unroll
    for(int o = 16; o; o >>= 1){
        s.x += __shfl_xor_sync(~0u, s.x, o); s.y += __shfl_xor_sync(~0u, s.y, o);
        s.z += __shfl_xor_sync(~0u, s.z, o); s.w += __shfl_xor_sync(~0u, s.w, o);
        mx.x = fmaxf(mx.x, __shfl_xor_sync(~0u, mx.x, o)); mx.y = fmaxf(mx.y, __shfl_xor_sync(~0u, mx.y, o));
        mx.z = fmaxf(mx.z, __shfl_xor_sync(~0u, mx.z, o)); mx.w = fmaxf(mx.w, __shfl_xor_sync(~0u, mx.w, o));
        mn.x = fminf(mn.x, __shfl_xor_sync(~0u, mn.x, o)); mn.y = fminf(mn.y, __shfl_xor_sync(~0u, mn.y, o));
        mn.z = fminf(mn.z, __shfl_xor_sync(~0u, mn.z, o)); mn.w = fminf(mn.w, __shfl_xor_sync(~0u, mn.w, o));
    }

    __shared__ float4 ps[8], pxm[8], pnm[8];
    int w = tid >> 5, lane = tid & 31;
    if(lane == 0){ ps[w] = s; pxm[w] = mx; pnm[w] = mn; }
    __syncthreads();
    if(tid < 8){
        s = ps[tid]; mx = pxm[tid]; mn = pnm[tid];
        #pragma unroll
        for(int o = 4; o; o >>= 1){
            s.x += __shfl_xor_sync(0xff, s.x, o); s.y += __shfl_xor_sync(0xff, s.y, o);
            s.z += __shfl_xor_sync(0xff, s.z, o); s.w += __shfl_xor_sync(0xff, s.w, o);
            mx.x = fmaxf(mx.x, __shfl_xor_sync(0xff, mx.x, o)); mx.y = fmaxf(mx.y, __shfl_xor_sync(0xff, mx.y, o));
            mx.z = fmaxf(mx.z, __shfl_xor_sync(0xff, mx.z, o)); mx.w = fmaxf(mx.w, __shfl_xor_sync(0xff, mx.w, o));
            mn.x = fminf(mn.x, __shfl_xor_sync(0xff, mn.x, o)); mn.y = fminf(mn.y, __shfl_xor_sync(0xff, mn.y, o));
            mn.z = fminf(mn.z, __shfl_xor_sync(0xff, mn.z, o)); mn.w = fminf(mn.w, __shfl_xor_sync(0xff, mn.w, o));
        }
        if(tid == 0){
            g_ssum[b*NCH+ch] = s; g_smax[b*NCH+ch] = mx; g_smin[b*NCH+ch] = mn;
        }
    }
}

// ---------------- STFT: 4 frames/block, register radix DFT-16 + constant DFT-20 ----------------
__global__ void k_stft(const float* __restrict__ x, const float* __restrict__ win){
    const float C16[16] = { 1.f, 0.9238795325f, 0.7071067812f, 0.3826834324f, 0.f,
                           -0.3826834324f,-0.7071067812f,-0.9238795325f,-1.f,-0.9238795325f,
                           -0.7071067812f,-0.3826834324f, 0.f, 0.3826834324f, 0.7071067812f, 0.9238795325f };
    const float S16[16] = { 0.f, 0.3826834324f, 0.7071067812f, 0.9238795325f, 1.f,
                            0.9238795325f, 0.7071067812f, 0.3826834324f, 0.f,-0.3826834324f,
                           -0.7071067812f,-0.9238795325f,-1.f,-0.9238795325f,-0.7071067812f,-0.3826834324f };
    const float C20[20] = { 1.f, 0.9510565163f, 0.8090169944f, 0.5877852523f, 0.3090169944f,
                            0.f,-0.3090169944f,-0.5877852523f,-0.8090169944f,-0.9510565163f,
                           -1.f,-0.9510565163f,-0.8090169944f,-0.5877852523f,-0.3090169944f,
                            0.f, 0.3090169944f, 0.5877852523f, 0.8090169944f, 0.9510565163f };
    const float S20[20] = { 0.f, 0.3090169944f, 0.5877852523f, 0.8090169944f, 0.9510565163f,
                            1.f, 0.9510565163f, 0.8090169944f, 0.5877852523f, 0.3090169944f,
                            0.f,-0.3090169944f,-0.5877852523f,-0.8090169944f,-0.9510565163f,
                           -1.f,-0.9510565163f,-0.8090169944f,-0.5877852523f,-0.3090169944f };

    int blk = blockIdx.x, b = blockIdx.y;
    int tid = threadIdx.x;
    int t0 = blk*TS4;
    __shared__ float  sv[C_][SVLEN];
    __shared__ float  swin[NFFT_];
    __shared__ float2 sG[TS4][C_][9][20];
    __shared__ float  sMean[4];
    __shared__ float  sInv;

    if(tid < 32){
        float4 s  = make_float4(0.f,0.f,0.f,0.f);
        float4 mx = make_float4(-1e30f,-1e30f,-1e30f,-1e30f);
        float4 mn = make_float4( 1e30f, 1e30f, 1e30f, 1e30f);
        for(int i = tid; i < NCH; i += 32){
            float4 a = g_ssum[b*NCH+i];
            s.x += a.x; s.y += a.y; s.z += a.z; s.w += a.w;
            float4 c = g_smax[b*NCH+i];
            mx.x = fmaxf(mx.x,c.x); mx.y = fmaxf(mx.y,c.y); mx.z = fmaxf(mx.z,c.z); mx.w = fmaxf(mx.w,c.w);
            float4 d = g_smin[b*NCH+i];
            mn.x = fminf(mn.x,d.x); mn.y = fminf(mn.y,d.y); mn.z = fminf(mn.z,d.z); mn.w = fminf(mn.w,d.w);
        }
        for(int o = 16; o; o >>= 1){
            s.x += __shfl_xor_sync(~0u, s.x, o); s.y += __shfl_xor_sync(~0u, s.y, o);
            s.z += __shfl_xor_sync(~0u, s.z, o); s.w += __shfl_xor_sync(~0u, s.w, o);
            mx.x = fmaxf(mx.x, __shfl_xor_sync(~0u, mx.x, o)); mx.y = fmaxf(mx.y, __shfl_xor_sync(~0u, mx.y, o));
            mx.z = fmaxf(mx.z, __shfl_xor_sync(~0u, mx.z, o)); mx.w = fmaxf(mx.w, __shfl_xor_sync(~0u, mx.w, o));
            mn.x = fminf(mn.x, __shfl_xor_sync(~0u, mn.x, o)); mn.y = fminf(mn.y, __shfl_xor_sync(~0u, mn.y, o));
            mn.z = fminf(mn.z, __shfl_xor_sync(~0u, mn.z, o)); mn.w = fminf(mn.w, __shfl_xor_sync(~0u, mn.w, o));
        }
        if(tid == 0){
            float m0 = s.x/(float)L_, m1 = s.y/(float)L_, m2 = s.z/(float)L_, m3 = s.w/(float)L_;
            float a = fmaxf(fmaxf(mx.x-m0, m0-mn.x), fmaxf(mx.y-m1, m1-mn.y));
            a = fmaxf(a, fmaxf(fmaxf(mx.z-m2, m2-mn.z), fmaxf(mx.w-m3, m3-mn.w)));
            sMean[0]=m0; sMean[1]=m1; sMean[2]=m2; sMean[3]=m3; sInv = 1.0f/a;
        }
    }
    for(int i = tid; i < NFFT_; i += 256) swin[i] = win[i];
    __syncthreads();

    {
        float m0 = sMean[0], m1 = sMean[1], m2 = sMean[2], m3 = sMean[3], inv = sInv;
        for(int i = tid; i < SVLEN; i += 256){
            int l = t0*HOP_ + i - (NFFT_/2);
            if(l < 0) l = -l;
            else if(l >= L_) l = 2*L_ - 2 - l;
            float4 v = *(const float4*)(x + ((size_t)b*L_ + l)*C_);
            sv[0][i] = (v.x-m0)*inv; sv[1][i] = (v.y-m1)*inv;
            sv[2][i] = (v.z-m2)*inv; sv[3][i] = (v.w-m3)*inv;
        }
    }
    __syncthreads();

    for(int task = tid; task < TS4*C_*20; task += 256){
        int r = task % 20;
        int c = (task/20) & 3;
        int f = task/80;
        int base = f*HOP_ + r;
        float v[16];
        #pragma unroll
        for(int q = 0; q < 16; q++) v[q] = sv[c][base + 20*q] * swin[20*q + r];
        float2 Bq[4][4];
        #pragma unroll
        for(int qb = 0; qb < 4; qb++){
            float v0=v[qb], v1=v[4+qb], v2=v[8+qb], v3=v[12+qb];
            float s0=v0+v2, d0=v0-v2, s1=v1+v3, d1=v1-v3;
            Bq[qb][0] = make_float2(s0+s1, 0.f);
            Bq[qb][2] = make_float2(s0-s1, 0.f);
            Bq[qb][1] = make_float2(d0, -d1);
            Bq[qb][3] = make_float2(d0,  d1);
        }
        float sn, cs; sincospif(-(float)r/160.0f, &sn, &cs);
        float2 step = make_float2(cs, sn), w = make_float2(1.f, 0.f);
        #pragma unroll
        for(int m = 0; m < 9; m++){
            float2 acc = Bq[0][m&3];
            #pragma unroll
            for(int qb = 1; qb < 4; qb++){
                int j = (qb*m) & 15;
                float2 y = Bq[qb][m&3];
                acc.x += y.x*C16[j] + y.y*S16[j];
                acc.y += y.y*C16[j] - y.x*S16[j];
            }
            sG[f][c][m][r] = cmul(acc, w);
            w = cmul(w, step);
        }
    }
    __syncthreads();

    for(int task = tid; task < TS4*C_*16; task += 256){
        int m = task & 15;
        int c = (task >> 4) & 3;
        int f = task >> 6;
        int t = t0 + f;
        if(t >= T_) continue;
        float2 y[20];
        if(m <= 8){
            #pragma unroll
            for(int r = 0; r < 20; r++) y[r] = sG[f][c][m][r];
        } else {
            int mm = 16 - m;
            #pragma unroll
            for(int r = 0; r < 20; r++){
                float2 g = sG[f][c][mm][r];
                float gr = g.x, gi = -g.y;
                y[r].x = gr*C20[r] + gi*S20[r];
                y[r].y = gi*C20[r] - gr*S20[r];
            }
        }
        float2 D[5][4];
        #pragma unroll
        for(int r2 = 0; r2 < 5; r2++){
            float2 y0=y[r2], y1=y[5+r2], y2=y[10+r2], y3=y[15+r2];
            float2 s0=cadd(y0,y2), d0=csub(y0,y2), s1=cadd(y1,y3), d1=csub(y1,y3);
            D[r2][0] = cadd(s0,s1);
            D[r2][2] = csub(s0,s1);
            D[r2][1] = make_float2(d0.x + d1.y, d0.y - d1.x);
            D[r2][3] = make_float2(d0.x - d1.y, d0.y + d1.x);
        }
        int amax = (m == 0) ? 10 : 9;
        #pragma unroll
        for(int a = 0; a <= 10; a++){
            if(a > amax) break;
            float2 acc = D[0][a&3];
            #pragma unroll
            for(int r2 = 1; r2 < 5; r2++){
                int j = (a*r2) % 20;
                float2 dd = D[r2][a&3];
                acc.x += dd.x*C20[j] + dd.y*S20[j];
                acc.y += dd.y*C20[j] - dd.x*S20[j];
            }
            int k = 16*a + m;
            g_X[(((size_t)b*T_ + t)*F_ + k)*C_ + c] = acc;   // [b][t][k][c]
        }
    }
}

// ---------------- fused MVDR beam + ISTFT + OLA ----------------
struct LDLf { float iD0,iD1,iD2,iD3; float2 L10,L20,L30,L21,L31,L32; };

__device__ __forceinline__ float2 mvdr_beam2(const LDLf& f,
    float2 h1, float2 h2, float2 h3,          // h0 = 1
    float2 X0, float2 X1, float2 X2, float2 X3)
{
    float2 z1 = csub(h1, f.L10);
    float2 z2 = csub(csub(h2, f.L20), cmul(f.L21, z1));
    float2 z3 = csub(csub(csub(h3, f.L30), cmul(f.L31, z1)), cmul(f.L32, z2));
    float2 y3 = cscale(f.iD3, z3);
    float2 y2 = csub(cscale(f.iD2, z2), ccmul(f.L32, y3));
    float2 y1 = csub(csub(cscale(f.iD1, z1), ccmul(f.L21, y2)), ccmul(f.L31, y3));
    float2 y0 = csub(csub(csub(make_float2(f.iD0, 0.f), ccmul(f.L10, y1)), ccmul(f.L20, y2)), ccmul(f.L30, y3));
    float den = y0.x + (h1.x*y1.x + h1.y*y1.y) + (h2.x*y2.x + h2.y*y2.y) + (h3.x*y3.x + h3.y*y3.y);
    float2 s  = cadd(cadd(ccmul(y0,X0), ccmul(y1,X1)), cadd(ccmul(y2,X2), ccmul(y3,X3)));
    float inv = 1.0f/den;
    return make_float2(s.x*inv, s.y*inv);
}

#define SY_BYTES (2*TF*162*8)     // 20736
#define SFR_BYTES (2*TF*322*4)    // 20608

__global__ void __launch_bounds__(192) k_bistft(float* __restrict__ out){
    const float C20[20] = { 1.f, 0.9510565163f, 0.8090169944f, 0.5877852523f, 0.3090169944f,
                            0.f,-0.3090169944f,-0.5877852523f,-0.8090169944f,-0.9510565163f,
                           -1.f,-0.9510565163f,-0.8090169944f,-0.5877852523f,-0.3090169944f,
                            0.f, 0.3090169944f, 0.5877852523f, 0.8090169944f, 0.9510565163f };
    const float S20[20] = { 0.f, 0.3090169944f, 0.5877852523f, 0.8090169944f, 0.9510565163f,
                            1.f, 0.9510565163f, 0.8090169944f, 0.5877852523f, 0.3090169944f,
                            0.f,-0.3090169944f,-0.5877852523f,-0.8090169944f,-0.9510565163f,
                           -1.f,-0.9510565163f,-0.8090169944f,-0.5877852523f,-0.3090169944f };
    const float C16[16] = { 1.f, 0.9238795325f, 0.7071067812f, 0.3826834324f, 0.f,
                           -0.3826834324f,-0.7071067812f,-0.9238795325f,-1.f,-0.9238795325f,
                           -0.7071067812f,-0.3826834324f, 0.f, 0.3826834324f, 0.7071067812f, 0.9238795325f };
    const float S16[16] = { 0.f, 0.3826834324f, 0.7071067812f, 0.9238795325f, 1.f,
                            0.9238795325f, 0.7071067812f, 0.3826834324f, 0.f,-0.3826834324f,
                           -0.7071067812f,-0.9238795325f,-1.f,-0.9238795325f,-0.7071067812f,-0.3826834324f };

    int blk = blockIdx.x, b = blockIdx.y;
    int tid = threadIdx.x;
    int t0  = blk*NQ;

    __shared__ float2 sH[2][9][20][TF+1];
    __shared__ __align__(16) char pool[SY_BYTES > SFR_BYTES ? SY_BYTES : SFR_BYTES];
    float2* sY  = (float2*)pool;   // [ (beam*TF+f)*162 + k ]
    float*  sFr = (float*)pool;    // [ (beam*TF+f)*322 + n ]  (aliases sY, used after)

    // ======== phase 1: beam (161 threads, serial IIR chain over TF frames, both beams) ========
    if(tid < F_){
        int k = tid;
        const float4* gx = (const float4*)g_X + (size_t)b*T_*F_*2;   // [t][k] coalesced over k

        const float phi = (float)(6.283185307179586 * 50.0 * 0.027 * 0.6427876096865393 / 340.0);
        float ang = phi * (float)k;
        float s1, c1; sincosf(ang, &s1, &c1);
        float c2 = c1*c1 - s1*s1, s2 = 2.f*c1*s1;
        float c3 = c2*c1 - s2*s1, s3 = s2*c1 + c2*s1;

        float d0=0,d1=0,d2=0,d3=0;
        float2 m10={0,0}, m20={0,0}, m21={0,0}, m30={0,0}, m31={0,0}, m32={0,0};

        int tw = t0 - 1;
        if(tw >= 0){
            #pragma unroll
            for(int j = 0; j < KTAP; j++){
                int s = tw - j;
                if(s < 0) break;
                float cf = (s == 0) ? c_p05[tw] : c_c95[j];
                size_t off = ((size_t)s*F_ + k)*2;
                float4 a = gx[off], bb = gx[off+1];
                float2 y0 = make_float2(a.x,a.y), y1 = make_float2(a.z,a.w);
                float2 y2 = make_float2(bb.x,bb.y), y3 = make_float2(bb.z,bb.w);
                d0 += cf*(y0.x*y0.x + y0.y*y0.y);
                d1 += cf*(y1.x*y1.x + y1.y*y1.y);
                d2 += cf*(y2.x*y2.x + y2.y*y2.y);
                d3 += cf*(y3.x*y3.x + y3.y*y3.y);
                m10 = cadd(m10, cscale(cf, cmulc(y1,y0)));
                m20 = cadd(m20, cscale(cf, cmulc(y2,y0)));
                m21 = cadd(m21, cscale(cf, cmulc(y2,y1)));
                m30 = cadd(m30, cscale(cf, cmulc(y3,y0)));
                m31 = cadd(m31, cscale(cf, cmulc(y3,y1)));
                m32 = cadd(m32, cscale(cf, cmulc(y3,y2)));
            }
        }

        #pragma unroll
        for(int i = 0; i < TF; i++){
            int t = t0 + i;
            if(t < T_){
                size_t off = ((size_t)t*F_ + k)*2;
                float4 xa = gx[off], xb = gx[off+1];
                float2 X0 = make_float2(xa.x,xa.y), X1 = make_float2(xa.z,xa.w);
                float2 X2 = make_float2(xb.x,xb.y), X3 = make_float2(xb.z,xb.w);

                if(t == 0){
                    d0 = X0.x*X0.x + X0.y*X0.y;
                    d1 = X1.x*X1.x + X1.y*X1.y;
                    d2 = X2.x*X2.x + X2.y*X2.y;
                    d3 = X3.x*X3.x + X3.y*X3.y;
                    m10 = cmulc(X1,X0); m20 = cmulc(X2,X0); m21 = cmulc(X2,X1);
                    m30 = cmulc(X3,X0); m31 = cmulc(X3,X1); m32 = cmulc(X3,X2);
                } else {
                    d0 = 0.05f*d0 + 0.95f*(X0.x*X0.x + X0.y*X0.y);
                    d1 = 0.05f*d1 + 0.95f*(X1.x*X1.x + X1.y*X1.y);
                    d2 = 0.05f*d2 + 0.95f*(X2.x*X2.x + X2.y*X2.y);
                    d3 = 0.05f*d3 + 0.95f*(X3.x*X3.x + X3.y*X3.y);
                    m10 = cadd(cscale(0.05f,m10), cscale(0.95f, cmulc(X1,X0)));
                    m20 = cadd(cscale(0.05f,m20), cscale(0.95f, cmulc(X2,X0)));
                    m21 = cadd(cscale(0.05f,m21), cscale(0.95f, cmulc(X2,X1)));
                    m30 = cadd(cscale(0.05f,m30), cscale(0.95f, cmulc(X3,X0)));
                    m31 = cadd(cscale(0.05f,m31), cscale(0.95f, cmulc(X3,X1)));
                    m32 = cadd(cscale(0.05f,m32), cscale(0.95f, cmulc(X3,X2)));
                }

                float tr4 = 0.25f*(d0+d1+d2+d3);
                float a0 = d0+tr4, a1 = d1+tr4, a2 = d2+tr4, a3 = d3+tr4;

                LDLf f;
                f.iD0 = 1.0f/a0;
                f.L10 = cscale(f.iD0, m10); f.L20 = cscale(f.iD0, m20); f.L30 = cscale(f.iD0, m30);
                float D1 = a1 - (m10.x*f.L10.x + m10.y*f.L10.y);
                f.iD1 = 1.0f/D1;
                float2 t21 = csub(m21, cmulc(m20, f.L10));
                f.L21 = cscale(f.iD1, t21);
                float2 t31 = csub(m31, cmulc(m30, f.L10));
                f.L31 = cscale(f.iD1, t31);
                float D2 = a2 - (m20.x*f.L20.x + m20.y*f.L20.y) - (t21.x*f.L21.x + t21.y*f.L21.y);
                f.iD2 = 1.0f/D2;
                float2 t32 = csub(csub(m32, cmulc(m30, f.L20)), cmulc(t31, f.L21));
                f.L32 = cscale(f.iD2, t32);
                float D3 = a3 - (m30.x*f.L30.x + m30.y*f.L30.y)
                              - (t31.x*f.L31.x + t31.y*f.L31.y)
                              - (t32.x*f.L32.x + t32.y*f.L32.y);
                f.iD3 = 1.0f/D3;

                float2 o1 = mvdr_beam2(f, make_float2(c1,-s1), make_float2(c2,-s2), make_float2(c3,-s3),
                                       X0, X1, X2, X3);
                float2 o2 = mvdr_beam2(f, make_float2(c1, s1), make_float2(c2, s2), make_float2(c3, s3),
                                       X0, X1, X2, X3);
                sY[(0*TF+i)*162 + k] = o1;
                sY[(1*TF+i)*162 + k] = o2;
            } else {
                sY[(0*TF+i)*162 + k] = make_float2(0.f,0.f);
                sY[(1*TF+i)*162 + k] = make_float2(0.f,0.f);
            }
        }
    }
    __syncthreads();

    // ======== phase 2 (stage A): per (beam,k1,f) inverse DFT-20 -> sH ========
    if(tid < 2*9*TF){
        int beam = tid / (9*TF);
        int r    = tid % (9*TF);
        int k1 = r / TF, f = r % TF;
        const float2* yrow = sY + (beam*TF + f)*162;
        float2 z[20];
        #pragma unroll
        for(int k2 = 0; k2 < 20; k2++){
            int kk = 16*k2 + k1;
            float2 v;
            if(kk <= 160){
                v = yrow[kk];
                if(k1 == 0 && (k2 == 0 || k2 == 10)) v.y = 0.f;
            } else {
                v = yrow[320-kk];
                v.y = -v.y;
            }
            z[k2] = v;
        }
        float2 Y[5][4];
        #pragma unroll
        for(int bq = 0; bq < 5; bq++){
            float2 z0=z[bq], z1=z[bq+5], z2=z[bq+10], z3=z[bq+15];
            float2 s0=cadd(z0,z2), s1=csub(z0,z2), s2=cadd(z1,z3), s3=csub(z1,z3);
            Y[bq][0] = cadd(s0,s2);
            Y[bq][2] = csub(s0,s2);
            Y[bq][1] = make_float2(s1.x - s3.y, s1.y + s3.x);
            Y[bq][3] = make_float2(s1.x + s3.y, s1.y - s3.x);
        }
        float sc = (k1==0 || k1==8) ? 1.f : 2.f;
        #pragma unroll
        for(int p = 0; p < 20; p++){
            float2 acc = Y[0][p&3];
            #pragma unroll
            for(int bq = 1; bq < 5; bq++){
                float cw = C20[(bq*p)%20], sw = S20[(bq*p)%20];
                float2 y = Y[bq][p&3];
                acc.x += cw*y.x - sw*y.y;
                acc.y += cw*y.y + sw*y.x;
            }
            sH[beam][k1][p][f] = make_float2(sc*acc.x, sc*acc.y);
        }
    }
    __syncthreads();

    // ======== phase 3 (stage B): twiddle + 9-term DFT-16 -> sFr (aliases sY) ========
    for(int task = tid; task < 2*20*TF; task += 192){
        int beam = task / (20*TF);
        int r    = task % (20*TF);
        int pm = r / TF, f = r % TF;
        float sn, cs; sincospif((float)pm/160.0f, &sn, &cs);
        float2 wst = make_float2(cs, sn), w = make_float2(1.f, 0.f);
        float2 a[9];
        a[0] = sH[beam][0][pm][f];
        #pragma unroll
        for(int k1 = 1; k1 < 9; k1++){
            w = cmul(w, wst);
            a[k1] = cmul(sH[beam][k1][pm][f], w);
        }
        float* frow = sFr + (beam*TF + f)*322;
        #pragma unroll
        for(int u = 0; u < 16; u++){
            float acc = a[0].x;
            #pragma unroll
            for(int k1 = 1; k1 < 9; k1++){
                int j = (k1*u) & 15;
                acc += a[k1].x*C16[j] - a[k1].y*S16[j];
            }
            frow[20*u + pm] = acc * (1.0f/640.0f);
        }
    }
    __syncthreads();

    // ======== phase 4: OLA output ========
    int qmax = min(t0 + NQ, T_ - 1);
    int nq = qmax - t0;
    for(int task = tid; task < 2*nq*80; task += 192){
        int beam = task / (nq*80);
        int r2   = task % (nq*80);
        int qi = r2 / 80;
        int rr = (r2 % 80)*2;
        int q  = t0 + 1 + qi;
        int fq = qi + 1;
        const float* fa = sFr + (beam*TF + fq)*322;
        const float* fb = sFr + (beam*TF + fq - 1)*322;
        float v0 = fa[rr]   + fb[160+rr];
        float v1 = fa[rr+1] + fb[161+rr];
        *(float2*)(out + (size_t)(beam*B_+b)*L_ + (size_t)(q-1)*160 + rr) = make_float2(v0, v1);
    }
}

// ---------------- launch ----------------
extern "C" void kernel_launch(void* const* d_in, const int* in_sizes, int n_in,
                              void* d_out, int out_size){
    const float* x   = (const float*)d_in[0];
    const float* win = (const float*)d_in[1];
    float* out = (float*)d_out;

    k_stats <<<dim3(NCH, B_), 256>>>(x);
    k_stft  <<<dim3((T_+TS4-1)/TS4, B_), 256>>>(x, win);
    k_bistft<<<dim3((T_-1+NQ-1)/NQ, B_), 192>>>(out);
}

// round 14
// speedup vs baseline: 1.1801x; 1.0325x over previous
#include <cuda_runtime.h>
#include <math.h>

#define B_    8
#define L_    160000
#define C_    4
#define NFFT_ 320
#define HOP_  160
#define T_    1001
#define F_    161
#define KTAP  4
#define NQ    7          // fused: output q-segments per block
#define TF    8          // fused: frames per block
#define TS4   5          // stft: frames per block
#define SVLEN (160*TS4 + 160)   // 960
#define NCH   125        // stats chunks per batch
#define CHL   1280       // samples per chunk (5 x 256)

// ---------------- scratch ----------------
__device__ float2 g_X [(size_t)B_*T_*F_*C_];    // STFT  [b][t][k][c]
__device__ float4 g_ssum[B_*NCH];
__device__ float4 g_smax[B_*NCH];
__device__ float4 g_smin[B_*NCH];

__constant__ float c_c95[10] = {0.95f, 0.0475f, 2.375e-3f, 1.1875e-4f, 5.9375e-6f,
                                2.96875e-7f, 1.484375e-8f, 7.421875e-10f,
                                3.7109375e-11f, 1.85546875e-12f};
__constant__ float c_p05[10] = {1.0f, 0.05f, 2.5e-3f, 1.25e-4f, 6.25e-6f,
                                3.125e-7f, 1.5625e-8f, 7.8125e-10f,
                                3.90625e-11f, 1.953125e-12f};

// ---------------- complex helpers ----------------
__device__ __forceinline__ float2 cadd(float2 a, float2 b){ return make_float2(a.x+b.x, a.y+b.y); }
__device__ __forceinline__ float2 csub(float2 a, float2 b){ return make_float2(a.x-b.x, a.y-b.y); }
__device__ __forceinline__ float2 cmul(float2 a, float2 b){ return make_float2(a.x*b.x-a.y*b.y, a.x*b.y+a.y*b.x); }
__device__ __forceinline__ float2 ccmul(float2 a, float2 b){ return make_float2(a.x*b.x+a.y*b.y, a.x*b.y-a.y*b.x); } // conj(a)*b
__device__ __forceinline__ float2 cmulc(float2 a, float2 b){ return make_float2(a.x*b.x+a.y*b.y, a.y*b.x-a.x*b.y); } // a*conj(b)
__device__ __forceinline__ float2 cscale(float s, float2 a){ return make_float2(s*a.x, s*a.y); }

// ---------------- stats ----------------
__global__ void k_stats(const float* __restrict__ x){
    int b = blockIdx.y, ch = blockIdx.x;
    int tid = threadIdx.x;
    const float4* px = (const float4*)(x + (size_t)b*L_*C_) + ch*CHL + tid;

    float4 v0 = px[0], v1 = px[256], v2 = px[512], v3 = px[768], v4 = px[1024];

    float4 s, mx, mn;
    s.x = v0.x+v1.x+v2.x+v3.x+v4.x; s.y = v0.y+v1.y+v2.y+v3.y+v4.y;
    s.z = v0.z+v1.z+v2.z+v3.z+v4.z; s.w = v0.w+v1.w+v2.w+v3.w+v4.w;
    mx.x = fmaxf(fmaxf(fmaxf(v0.x,v1.x),fmaxf(v2.x,v3.x)),v4.x);
    mx.y = fmaxf(fmaxf(fmaxf(v0.y,v1.y),fmaxf(v2.y,v3.y)),v4.y);
    mx.z = fmaxf(fmaxf(fmaxf(v0.z,v1.z),fmaxf(v2.z,v3.z)),v4.z);
    mx.w = fmaxf(fmaxf(fmaxf(v0.w,v1.w),fmaxf(v2.w,v3.w)),v4.w);
    mn.x = fminf(fminf(fminf(v0.x,v1.x),fminf(v2.x,v3.x)),v4.x);
    mn.y = fminf(fminf(fminf(v0.y,v1.y),fminf(v2.y,v3.y)),v4.y);
    mn.z = fminf(fminf(fminf(v0.z,v1.z),fminf(v2.z,v3.z)),v4.z);
    mn.w = fminf(fminf(fminf(v0.w,v1.w),fminf(v2.w,v3.w)),v4.w);

    #pragma unroll
    for(int o = 16; o; o >>= 1){
        s.x += __shfl_xor_sync(~0u, s.x, o); s.y += __shfl_xor_sync(~0u, s.y, o);
        s.z += __shfl_xor_sync(~0u, s.z, o); s.w += __shfl_xor_sync(~0u, s.w, o);
        mx.x = fmaxf(mx.x, __shfl_xor_sync(~0u, mx.x, o)); mx.y = fmaxf(mx.y, __shfl_xor_sync(~0u, mx.y, o));
        mx.z = fmaxf(mx.z, __shfl_xor_sync(~0u, mx.z, o)); mx.w = fmaxf(mx.w, __shfl_xor_sync(~0u, mx.w, o));
        mn.x = fminf(mn.x, __shfl_xor_sync(~0u, mn.x, o)); mn.y = fminf(mn.y, __shfl_xor_sync(~0u, mn.y, o));
        mn.z = fminf(mn.z, __shfl_xor_sync(~0u, mn.z, o)); mn.w = fminf(mn.w, __shfl_xor_sync(~0u, mn.w, o));
    }

    __shared__ float4 ps[8], pxm[8], pnm[8];
    int w = tid >> 5, lane = tid & 31;
    if(lane == 0){ ps[w] = s; pxm[w] = mx; pnm[w] = mn; }
    __syncthreads();
    if(tid < 8){
        s = ps[tid]; mx = pxm[tid]; mn = pnm[tid];
        #pragma unroll
        for(int o = 4; o; o >>= 1){
            s.x += __shfl_xor_sync(0xff, s.x, o); s.y += __shfl_xor_sync(0xff, s.y, o);
            s.z += __shfl_xor_sync(0xff, s.z, o); s.w += __shfl_xor_sync(0xff, s.w, o);
            mx.x = fmaxf(mx.x, __shfl_xor_sync(0xff, mx.x, o)); mx.y = fmaxf(mx.y, __shfl_xor_sync(0xff, mx.y, o));
            mx.z = fmaxf(mx.z, __shfl_xor_sync(0xff, mx.z, o)); mx.w = fmaxf(mx.w, __shfl_xor_sync(0xff, mx.w, o));
            mn.x = fminf(mn.x, __shfl_xor_sync(0xff, mn.x, o)); mn.y = fminf(mn.y, __shfl_xor_sync(0xff, mn.y, o));
            mn.z = fminf(mn.z, __shfl_xor_sync(0xff, mn.z, o)); mn.w = fminf(mn.w, __shfl_xor_sync(0xff, mn.w, o));
        }
        if(tid == 0){
            g_ssum[b*NCH+ch] = s; g_smax[b*NCH+ch] = mx; g_smin[b*NCH+ch] = mn;
        }
    }
}

// ---------------- STFT: 5 frames/block, register radix DFT-16 + constant DFT-20 ----------------
__global__ void k_stft(const float* __restrict__ x, const float* __restrict__ win){
    const float C16[16] = { 1.f, 0.9238795325f, 0.7071067812f, 0.3826834324f, 0.f,
                           -0.3826834324f,-0.7071067812f,-0.9238795325f,-1.f,-0.9238795325f,
                           -0.7071067812f,-0.3826834324f, 0.f, 0.3826834324f, 0.7071067812f, 0.9238795325f };
    const float S16[16] = { 0.f, 0.3826834324f, 0.7071067812f, 0.9238795325f, 1.f,
                            0.9238795325f, 0.7071067812f, 0.3826834324f, 0.f,-0.3826834324f,
                           -0.7071067812f,-0.9238795325f,-1.f,-0.9238795325f,-0.7071067812f,-0.3826834324f };
    const float C20[20] = { 1.f, 0.9510565163f, 0.8090169944f, 0.5877852523f, 0.3090169944f,
                            0.f,-0.3090169944f,-0.5877852523f,-0.8090169944f,-0.9510565163f,
                           -1.f,-0.9510565163f,-0.8090169944f,-0.5877852523f,-0.3090169944f,
                            0.f, 0.3090169944f, 0.5877852523f, 0.8090169944f, 0.9510565163f };
    const float S20[20] = { 0.f, 0.3090169944f, 0.5877852523f, 0.8090169944f, 0.9510565163f,
                            1.f, 0.9510565163f, 0.8090169944f, 0.5877852523f, 0.3090169944f,
                            0.f,-0.3090169944f,-0.5877852523f,-0.8090169944f,-0.9510565163f,
                           -1.f,-0.9510565163f,-0.8090169944f,-0.5877852523f,-0.3090169944f };

    int blk = blockIdx.x, b = blockIdx.y;
    int tid = threadIdx.x;
    int t0 = blk*TS4;
    __shared__ float  sv[C_][SVLEN];
    __shared__ float  swin[NFFT_];
    __shared__ float2 sG[TS4][C_][9][20];
    __shared__ float  sMean[4];
    __shared__ float  sInv;

    if(tid < 32){
        float4 s  = make_float4(0.f,0.f,0.f,0.f);
        float4 mx = make_float4(-1e30f,-1e30f,-1e30f,-1e30f);
        float4 mn = make_float4( 1e30f, 1e30f, 1e30f, 1e30f);
        for(int i = tid; i < NCH; i += 32){
            float4 a = g_ssum[b*NCH+i];
            s.x += a.x; s.y += a.y; s.z += a.z; s.w += a.w;
            float4 c = g_smax[b*NCH+i];
            mx.x = fmaxf(mx.x,c.x); mx.y = fmaxf(mx.y,c.y); mx.z = fmaxf(mx.z,c.z); mx.w = fmaxf(mx.w,c.w);
            float4 d = g_smin[b*NCH+i];
            mn.x = fminf(mn.x,d.x); mn.y = fminf(mn.y,d.y); mn.z = fminf(mn.z,d.z); mn.w = fminf(mn.w,d.w);
        }
        for(int o = 16; o; o >>= 1){
            s.x += __shfl_xor_sync(~0u, s.x, o); s.y += __shfl_xor_sync(~0u, s.y, o);
            s.z += __shfl_xor_sync(~0u, s.z, o); s.w += __shfl_xor_sync(~0u, s.w, o);
            mx.x = fmaxf(mx.x, __shfl_xor_sync(~0u, mx.x, o)); mx.y = fmaxf(mx.y, __shfl_xor_sync(~0u, mx.y, o));
            mx.z = fmaxf(mx.z, __shfl_xor_sync(~0u, mx.z, o)); mx.w = fmaxf(mx.w, __shfl_xor_sync(~0u, mx.w, o));
            mn.x = fminf(mn.x, __shfl_xor_sync(~0u, mn.x, o)); mn.y = fminf(mn.y, __shfl_xor_sync(~0u, mn.y, o));
            mn.z = fminf(mn.z, __shfl_xor_sync(~0u, mn.z, o)); mn.w = fminf(mn.w, __shfl_xor_sync(~0u, mn.w, o));
        }
        if(tid == 0){
            float m0 = s.x/(float)L_, m1 = s.y/(float)L_, m2 = s.z/(float)L_, m3 = s.w/(float)L_;
            float a = fmaxf(fmaxf(mx.x-m0, m0-mn.x), fmaxf(mx.y-m1, m1-mn.y));
            a = fmaxf(a, fmaxf(fmaxf(mx.z-m2, m2-mn.z), fmaxf(mx.w-m3, m3-mn.w)));
            sMean[0]=m0; sMean[1]=m1; sMean[2]=m2; sMean[3]=m3; sInv = 1.0f/a;
        }
    }
    for(int i = tid; i < NFFT_; i += 256) swin[i] = win[i];
    __syncthreads();

    {
        float m0 = sMean[0], m1 = sMean[1], m2 = sMean[2], m3 = sMean[3], inv = sInv;
        for(int i = tid; i < SVLEN; i += 256){
            int l = t0*HOP_ + i - (NFFT_/2);
            if(l < 0) l = -l;
            else if(l >= L_) l = 2*L_ - 2 - l;
            float4 v = *(const float4*)(x + ((size_t)b*L_ + l)*C_);
            sv[0][i] = (v.x-m0)*inv; sv[1][i] = (v.y-m1)*inv;
            sv[2][i] = (v.z-m2)*inv; sv[3][i] = (v.w-m3)*inv;
        }
    }
    __syncthreads();

    for(int task = tid; task < TS4*C_*20; task += 256){
        int r = task % 20;
        int c = (task/20) & 3;
        int f = task/80;
        int base = f*HOP_ + r;
        float v[16];
        #pragma unroll
        for(int q = 0; q < 16; q++) v[q] = sv[c][base + 20*q] * swin[20*q + r];
        float2 Bq[4][4];
        #pragma unroll
        for(int qb = 0; qb < 4; qb++){
            float v0=v[qb], v1=v[4+qb], v2=v[8+qb], v3=v[12+qb];
            float s0=v0+v2, d0=v0-v2, s1=v1+v3, d1=v1-v3;
            Bq[qb][0] = make_float2(s0+s1, 0.f);
            Bq[qb][2] = make_float2(s0-s1, 0.f);
            Bq[qb][1] = make_float2(d0, -d1);
            Bq[qb][3] = make_float2(d0,  d1);
        }
        float sn, cs; sincospif(-(float)r/160.0f, &sn, &cs);
        float2 step = make_float2(cs, sn), w = make_float2(1.f, 0.f);
        #pragma unroll
        for(int m = 0; m < 9; m++){
            float2 acc = Bq[0][m&3];
            #pragma unroll
            for(int qb = 1; qb < 4; qb++){
                int j = (qb*m) & 15;
                float2 y = Bq[qb][m&3];
                acc.x += y.x*C16[j] + y.y*S16[j];
                acc.y += y.y*C16[j] - y.x*S16[j];
            }
            sG[f][c][m][r] = cmul(acc, w);
            w = cmul(w, step);
        }
    }
    __syncthreads();

    for(int task = tid; task < TS4*C_*16; task += 256){
        int m = task & 15;
        int c = (task >> 4) & 3;
        int f = task >> 6;
        int t = t0 + f;
        if(t >= T_) continue;
        float2 y[20];
        if(m <= 8){
            #pragma unroll
            for(int r = 0; r < 20; r++) y[r] = sG[f][c][m][r];
        } else {
            int mm = 16 - m;
            #pragma unroll
            for(int r = 0; r < 20; r++){
                float2 g = sG[f][c][mm][r];
                float gr = g.x, gi = -g.y;
                y[r].x = gr*C20[r] + gi*S20[r];
                y[r].y = gi*C20[r] - gr*S20[r];
            }
        }
        float2 D[5][4];
        #pragma unroll
        for(int r2 = 0; r2 < 5; r2++){
            float2 y0=y[r2], y1=y[5+r2], y2=y[10+r2], y3=y[15+r2];
            float2 s0=cadd(y0,y2), d0=csub(y0,y2), s1=cadd(y1,y3), d1=csub(y1,y3);
            D[r2][0] = cadd(s0,s1);
            D[r2][2] = csub(s0,s1);
            D[r2][1] = make_float2(d0.x + d1.y, d0.y - d1.x);
            D[r2][3] = make_float2(d0.x - d1.y, d0.y + d1.x);
        }
        int amax = (m == 0) ? 10 : 9;
        #pragma unroll
        for(int a = 0; a <= 10; a++){
            if(a > amax) break;
            float2 acc = D[0][a&3];
            #pragma unroll
            for(int r2 = 1; r2 < 5; r2++){
                int j = (a*r2) % 20;
                float2 dd = D[r2][a&3];
                acc.x += dd.x*C20[j] + dd.y*S20[j];
                acc.y += dd.y*C20[j] - dd.x*S20[j];
            }
            int k = 16*a + m;
            g_X[(((size_t)b*T_ + t)*F_ + k)*C_ + c] = acc;   // [b][t][k][c]
        }
    }
}

// ---------------- fused MVDR beam + ISTFT + OLA ----------------
struct LDLf { float iD0,iD1,iD2,iD3; float2 L10,L20,L30,L21,L31,L32; };

#define SY_BYTES (2*TF*162*8)     // 20736
#define SFR_BYTES (2*TF*322*4)    // 20608

__global__ void __launch_bounds__(192) k_bistft(float* __restrict__ out){
    const float C20[20] = { 1.f, 0.9510565163f, 0.8090169944f, 0.5877852523f, 0.3090169944f,
                            0.f,-0.3090169944f,-0.5877852523f,-0.8090169944f,-0.9510565163f,
                           -1.f,-0.9510565163f,-0.8090169944f,-0.5877852523f,-0.3090169944f,
                            0.f, 0.3090169944f, 0.5877852523f, 0.8090169944f, 0.9510565163f };
    const float S20[20] = { 0.f, 0.3090169944f, 0.5877852523f, 0.8090169944f, 0.9510565163f,
                            1.f, 0.9510565163f, 0.8090169944f, 0.5877852523f, 0.3090169944f,
                            0.f,-0.3090169944f,-0.5877852523f,-0.8090169944f,-0.9510565163f,
                           -1.f,-0.9510565163f,-0.8090169944f,-0.5877852523f,-0.3090169944f };
    const float C16[16] = { 1.f, 0.9238795325f, 0.7071067812f, 0.3826834324f, 0.f,
                           -0.3826834324f,-0.7071067812f,-0.9238795325f,-1.f,-0.9238795325f,
                           -0.7071067812f,-0.3826834324f, 0.f, 0.3826834324f, 0.7071067812f, 0.9238795325f };
    const float S16[16] = { 0.f, 0.3826834324f, 0.7071067812f, 0.9238795325f, 1.f,
                            0.9238795325f, 0.7071067812f, 0.3826834324f, 0.f,-0.3826834324f,
                           -0.7071067812f,-0.9238795325f,-1.f,-0.9238795325f,-0.7071067812f,-0.3826834324f };

    int blk = blockIdx.x, b = blockIdx.y;
    int tid = threadIdx.x;
    int t0  = blk*NQ;

    __shared__ float2 sH[2][9][20][TF+1];
    __shared__ __align__(16) char pool[SY_BYTES > SFR_BYTES ? SY_BYTES : SFR_BYTES];
    float2* sY  = (float2*)pool;   // [ (beam*TF+f)*162 + k ]
    float*  sFr = (float*)pool;    // [ (beam*TF+f)*322 + n ]  (aliases sY, used after)

    // ======== phase 1: beam (161 threads, serial IIR chain over TF frames, both beams) ========
    if(tid < F_){
        int k = tid;
        const float4* gx = (const float4*)g_X + (size_t)b*T_*F_*2;   // [t][k] coalesced over k

        const float phi = (float)(6.283185307179586 * 50.0 * 0.027 * 0.6427876096865393 / 340.0);
        float ang = phi * (float)k;
        float s1, c1; sincosf(ang, &s1, &c1);
        float c2 = c1*c1 - s1*s1, s2 = 2.f*c1*s1;
        float c3 = c2*c1 - s2*s1, s3 = s2*c1 + c2*s1;

        float d0=0,d1=0,d2=0,d3=0;
        float2 m10={0,0}, m20={0,0}, m21={0,0}, m30={0,0}, m31={0,0}, m32={0,0};

        int tw = t0 - 1;
        if(tw >= 0){
            #pragma unroll
            for(int j = 0; j < KTAP; j++){
                int s = tw - j;
                if(s < 0) break;
                float cf = (s == 0) ? c_p05[tw] : c_c95[j];
                size_t off = ((size_t)s*F_ + k)*2;
                float4 a = gx[off], bb = gx[off+1];
                float2 y0 = make_float2(a.x,a.y), y1 = make_float2(a.z,a.w);
                float2 y2 = make_float2(bb.x,bb.y), y3 = make_float2(bb.z,bb.w);
                d0 += cf*(y0.x*y0.x + y0.y*y0.y);
                d1 += cf*(y1.x*y1.x + y1.y*y1.y);
                d2 += cf*(y2.x*y2.x + y2.y*y2.y);
                d3 += cf*(y3.x*y3.x + y3.y*y3.y);
                m10 = cadd(m10, cscale(cf, cmulc(y1,y0)));
                m20 = cadd(m20, cscale(cf, cmulc(y2,y0)));
                m21 = cadd(m21, cscale(cf, cmulc(y2,y1)));
                m30 = cadd(m30, cscale(cf, cmulc(y3,y0)));
                m31 = cadd(m31, cscale(cf, cmulc(y3,y1)));
                m32 = cadd(m32, cscale(cf, cmulc(y3,y2)));
            }
        }

        #pragma unroll
        for(int i = 0; i < TF; i++){
            int t = t0 + i;
            if(t < T_){
                size_t off = ((size_t)t*F_ + k)*2;
                float4 xa = gx[off], xb = gx[off+1];
                float2 X0 = make_float2(xa.x,xa.y), X1 = make_float2(xa.z,xa.w);
                float2 X2 = make_float2(xb.x,xb.y), X3 = make_float2(xb.z,xb.w);

                if(t == 0){
                    d0 = X0.x*X0.x + X0.y*X0.y;
                    d1 = X1.x*X1.x + X1.y*X1.y;
                    d2 = X2.x*X2.x + X2.y*X2.y;
                    d3 = X3.x*X3.x + X3.y*X3.y;
                    m10 = cmulc(X1,X0); m20 = cmulc(X2,X0); m21 = cmulc(X2,X1);
                    m30 = cmulc(X3,X0); m31 = cmulc(X3,X1); m32 = cmulc(X3,X2);
                } else {
                    d0 = 0.05f*d0 + 0.95f*(X0.x*X0.x + X0.y*X0.y);
                    d1 = 0.05f*d1 + 0.95f*(X1.x*X1.x + X1.y*X1.y);
                    d2 = 0.05f*d2 + 0.95f*(X2.x*X2.x + X2.y*X2.y);
                    d3 = 0.05f*d3 + 0.95f*(X3.x*X3.x + X3.y*X3.y);
                    m10 = cadd(cscale(0.05f,m10), cscale(0.95f, cmulc(X1,X0)));
                    m20 = cadd(cscale(0.05f,m20), cscale(0.95f, cmulc(X2,X0)));
                    m21 = cadd(cscale(0.05f,m21), cscale(0.95f, cmulc(X2,X1)));
                    m30 = cadd(cscale(0.05f,m30), cscale(0.95f, cmulc(X3,X0)));
                    m31 = cadd(cscale(0.05f,m31), cscale(0.95f, cmulc(X3,X1)));
                    m32 = cadd(cscale(0.05f,m32), cscale(0.95f, cmulc(X3,X2)));
                }

                float tr4 = 0.25f*(d0+d1+d2+d3);
                float a0 = d0+tr4, a1 = d1+tr4, a2 = d2+tr4, a3 = d3+tr4;

                // LDL^H
                LDLf f;
                f.iD0 = 1.0f/a0;
                f.L10 = cscale(f.iD0, m10); f.L20 = cscale(f.iD0, m20); f.L30 = cscale(f.iD0, m30);
                float D1 = a1 - (m10.x*f.L10.x + m10.y*f.L10.y);
                f.iD1 = 1.0f/D1;
                float2 t21 = csub(m21, cmulc(m20, f.L10));
                f.L21 = cscale(f.iD1, t21);
                float2 t31 = csub(m31, cmulc(m30, f.L10));
                f.L31 = cscale(f.iD1, t31);
                float D2 = a2 - (m20.x*f.L20.x + m20.y*f.L20.y) - (t21.x*f.L21.x + t21.y*f.L21.y);
                f.iD2 = 1.0f/D2;
                float2 t32 = csub(csub(m32, cmulc(m30, f.L20)), cmulc(t31, f.L21));
                f.L32 = cscale(f.iD2, t32);
                float D3 = a3 - (m30.x*f.L30.x + m30.y*f.L30.y)
                              - (t31.x*f.L31.x + t31.y*f.L31.y)
                              - (t32.x*f.L32.x + t32.y*f.L32.y);
                f.iD3 = 1.0f/D3;

                // shared forward solve: zX = L^{-1} X, then u = D^{-1} zX
                float2 v1 = csub(X1, cmul(f.L10, X0));
                float2 v2 = csub(csub(X2, cmul(f.L20, X0)), cmul(f.L21, v1));
                float2 v3 = csub(csub(csub(X3, cmul(f.L30, X0)), cmul(f.L31, v1)), cmul(f.L32, v2));
                float2 u0 = cscale(f.iD0, X0);
                float2 u1 = cscale(f.iD1, v1);
                float2 u2 = cscale(f.iD2, v2);
                float2 u3 = cscale(f.iD3, v3);

                // per-beam: z = L^{-1} h (z0 = 1), den = sum iD_i |z_i|^2, num = sum iD_i conj(z_i) zX_i
                #pragma unroll
                for(int beam = 0; beam < 2; beam++){
                    float bs = (beam == 0) ? -1.f : 1.f;
                    float2 h1 = make_float2(c1, bs*s1);
                    float2 h2 = make_float2(c2, bs*s2);
                    float2 h3 = make_float2(c3, bs*s3);
                    float2 z1 = csub(h1, f.L10);
                    float2 z2 = csub(csub(h2, f.L20), cmul(f.L21, z1));
                    float2 z3 = csub(csub(csub(h3, f.L30), cmul(f.L31, z1)), cmul(f.L32, z2));
                    float den = f.iD0
                              + f.iD1*(z1.x*z1.x + z1.y*z1.y)
                              + f.iD2*(z2.x*z2.x + z2.y*z2.y)
                              + f.iD3*(z3.x*z3.x + z3.y*z3.y);
                    float2 num = cadd(cadd(u0, ccmul(z1, u1)), cadd(ccmul(z2, u2), ccmul(z3, u3)));
                    sY[(beam*TF+i)*162 + k] = cscale(1.0f/den, num);
                }
            } else {
                sY[(0*TF+i)*162 + k] = make_float2(0.f,0.f);
                sY[(1*TF+i)*162 + k] = make_float2(0.f,0.f);
            }
        }
    }
    __syncthreads();

    // ======== phase 2 (stage A): per (beam,k1,f) inverse DFT-20 -> sH ========
    if(tid < 2*9*TF){
        int beam = tid / (9*TF);
        int r    = tid % (9*TF);
        int k1 = r / TF, f = r % TF;
        const float2* yrow = sY + (beam*TF + f)*162;
        float2 z[20];
        #pragma unroll
        for(int k2 = 0; k2 < 20; k2++){
            int kk = 16*k2 + k1;
            float2 v;
            if(kk <= 160){
                v = yrow[kk];
                if(k1 == 0 && (k2 == 0 || k2 == 10)) v.y = 0.f;
            } else {
                v = yrow[320-kk];
                v.y = -v.y;
            }
            z[k2] = v;
        }
        float2 Y[5][4];
        #pragma unroll
        for(int bq = 0; bq < 5; bq++){
            float2 z0=z[bq], z1=z[bq+5], z2=z[bq+10], z3=z[bq+15];
            float2 s0=cadd(z0,z2), s1=csub(z0,z2), s2=cadd(z1,z3), s3=csub(z1,z3);
            Y[bq][0] = cadd(s0,s2);
            Y[bq][2] = csub(s0,s2);
            Y[bq][1] = make_float2(s1.x - s3.y, s1.y + s3.x);
            Y[bq][3] = make_float2(s1.x + s3.y, s1.y - s3.x);
        }
        float sc = (k1==0 || k1==8) ? 1.f : 2.f;
        #pragma unroll
        for(int p = 0; p < 20; p++){
            float2 acc = Y[0][p&3];
            #pragma unroll
            for(int bq = 1; bq < 5; bq++){
                float cw = C20[(bq*p)%20], sw = S20[(bq*p)%20];
                float2 y = Y[bq][p&3];
                acc.x += cw*y.x - sw*y.y;
                acc.y += cw*y.y + sw*y.x;
            }
            sH[beam][k1][p][f] = make_float2(sc*acc.x, sc*acc.y);
        }
    }
    __syncthreads();

    // ======== phase 3 (stage B): twiddle + 9-term DFT-16 -> sFr (aliases sY) ========
    for(int task = tid; task < 2*20*TF; task += 192){
        int beam = task / (20*TF);
        int r    = task % (20*TF);
        int pm = r / TF, f = r % TF;
        float sn, cs; sincospif((float)pm/160.0f, &sn, &cs);
        float2 wst = make_float2(cs, sn), w = make_float2(1.f, 0.f);
        float2 a[9];
        a[0] = sH[beam][0][pm][f];
        #pragma unroll
        for(int k1 = 1; k1 < 9; k1++){
            w = cmul(w, wst);
            a[k1] = cmul(sH[beam][k1][pm][f], w);
        }
        float* frow = sFr + (beam*TF + f)*322;
        #pragma unroll
        for(int u = 0; u < 16; u++){
            float acc = a[0].x;
            #pragma unroll
            for(int k1 = 1; k1 < 9; k1++){
                int j = (k1*u) & 15;
                acc += a[k1].x*C16[j] - a[k1].y*S16[j];
            }
            frow[20*u + pm] = acc * (1.0f/640.0f);
        }
    }
    __syncthreads();

    // ======== phase 4: OLA output ========
    int qmax = min(t0 + NQ, T_ - 1);
    int nq = qmax - t0;
    for(int task = tid; task < 2*nq*80; task += 192){
        int beam = task / (nq*80);
        int r2   = task % (nq*80);
        int qi = r2 / 80;
        int rr = (r2 % 80)*2;
        int q  = t0 + 1 + qi;
        int fq = qi + 1;
        const float* fa = sFr + (beam*TF + fq)*322;
        const float* fb = sFr + (beam*TF + fq - 1)*322;
        float v0 = fa[rr]   + fb[160+rr];
        float v1 = fa[rr+1] + fb[161+rr];
        *(float2*)(out + (size_t)(beam*B_+b)*L_ + (size_t)(q-1)*160 + rr) = make_float2(v0, v1);
    }
}

// ---------------- launch ----------------
extern "C" void kernel_launch(void* const* d_in, const int* in_sizes, int n_in,
                              void* d_out, int out_size){
    const float* x   = (const float*)d_in[0];
    const float* win = (const float*)d_in[1];
    float* out = (float*)d_out;

    k_stats <<<dim3(NCH, B_), 256>>>(x);
    k_stft  <<<dim3((T_+TS4-1)/TS4, B_), 256>>>(x, win);
    k_bistft<<<dim3((T_-1+NQ-1)/NQ, B_), 192>>>(out);
}